// round 9
// baseline (speedup 1.0000x reference)
#include <cuda_runtime.h>
#include <cuda_fp16.h>
#include <cuda_fp8.h>
#include <math.h>
#include <cstdint>

#define BATCH 4096
#define UNITS 1024
#define OUT_STEPS 200
#define SEQ_LEN 5

#define BM 128
#define BN 128           // permuted z columns (= 32 units x 4 gates)
#define NTHREADS 256

#define NF8 8            // fp8 stages: K=1024 e4m3, 128 elems/stage
#define NF16 16          // fp16 stages: K=1024 half, 64 elems/stage
#define NSTG (NF8 + NF16)  // 24

#define A_STG 16384                     // 128 rows x 128B
#define B_STG 16384
#define STG_BYTES (A_STG + B_STG)       // 32KB
#define NBUF 3
#define SMEM_TOTAL (NBUF * STG_BYTES)   // 96KB -> 2 CTAs/SM

#define LO_SCALE 1048576.0f             // 2^20
#define LO_UNSCALE 9.5367431640625e-7f  // 2^-20

// ---------------- device globals ----------------
__device__ __half  g_Ah[2][BATCH * 1024];   // ping-pong h, fp16
__device__ uint8_t g_Aq[2][BATCH * 1024];   // ping-pong h, e4m3
__device__ __half  g_Bh[4096 * 1024];       // permuted R_hi fp16, row C, K-major
__device__ uint8_t g_Bq[4096 * 1024];       // permuted (R_lo * 2^20) e4m3
__device__ float g_c[BATCH * UNITS];
__device__ float g_pred[BATCH];
__device__ float g_kwP[4096];
__device__ float g_biasP[4096];

// ---------------- helpers ----------------
__device__ __forceinline__ uint32_t smem_u32(const void* p) {
    uint32_t a;
    asm("{ .reg .u64 t; cvta.to.shared.u64 t, %1; cvt.u32.u64 %0, t; }" : "=r"(a) : "l"(p));
    return a;
}
__device__ __forceinline__ void cp16(uint32_t saddr, const void* gaddr) {
    asm volatile("cp.async.cg.shared.global [%0], [%1], 16;" :: "r"(saddr), "l"(gaddr));
}
__device__ __forceinline__ void cp_commit() {
    asm volatile("cp.async.commit_group;" ::: "memory");
}
template<int N> __device__ __forceinline__ void cp_wait() {
    asm volatile("cp.async.wait_group %0;" :: "n"(N) : "memory");
}
__device__ __forceinline__ void ldsm4(uint32_t* r, uint32_t addr) {
    asm volatile("ldmatrix.sync.aligned.m8n8.x4.shared.b16 {%0,%1,%2,%3}, [%4];"
                 : "=r"(r[0]), "=r"(r[1]), "=r"(r[2]), "=r"(r[3]) : "r"(addr));
}
__device__ __forceinline__ void mma16816(float* c, const uint32_t* a, const uint32_t* b) {
    asm volatile(
        "mma.sync.aligned.m16n8k16.row.col.f32.f16.f16.f32 "
        "{%0,%1,%2,%3}, {%4,%5,%6,%7}, {%8,%9}, {%0,%1,%2,%3};"
        : "+f"(c[0]), "+f"(c[1]), "+f"(c[2]), "+f"(c[3])
        : "r"(a[0]), "r"(a[1]), "r"(a[2]), "r"(a[3]), "r"(b[0]), "r"(b[1]));
}
__device__ __forceinline__ void qmma16832(float* c, const uint32_t* a, const uint32_t* b) {
    asm volatile(
        "mma.sync.aligned.m16n8k32.row.col.f32.e4m3.e4m3.f32 "
        "{%0,%1,%2,%3}, {%4,%5,%6,%7}, {%8,%9}, {%0,%1,%2,%3};"
        : "+f"(c[0]), "+f"(c[1]), "+f"(c[2]), "+f"(c[3])
        : "r"(a[0]), "r"(a[1]), "r"(a[2]), "r"(a[3]), "r"(b[0]), "r"(b[1]));
}
__device__ __forceinline__ float sigm(float x) { return 1.0f / (1.0f + __expf(-x)); }
__device__ __forceinline__ float tanh_fast(float x) {
    float t = __expf(-2.0f * fabsf(x));
    float r = (1.0f - t) / (1.0f + t);
    return copysignf(r, x);
}

// ---------------- prep: build permuted split B (fp16 hi + scaled e4m3 lo) ----------------
// Permuted column C <- (unit u, gate g):
//   C = (u>>4)*64 + (g>>1)*32 + (u&3)*8 + ((u>>2)&3)*2 + (g&1)
// Inverse: u = (C>>6)*16 + ((C>>1)&3)*4 + ((C>>3)&3) ; g = ((C>>5)&1)*2 + (C&1)
__global__ void prep_kernel(const float* __restrict__ R, const float* __restrict__ Kw,
                            const float* __restrict__ bias) {
    int idx = blockIdx.x * blockDim.x + threadIdx.x;   // np*1024 + k
    if (idx >= 4096 * 1024) return;
    int np = idx >> 10;
    int k  = idx & 1023;
    int u = ((np >> 6) << 4) | (((np >> 1) & 3) << 2) | ((np >> 3) & 3);
    int g = (((np >> 5) & 1) << 1) | (np & 1);
    int n = g * 1024 + u;
    float v = R[k * 4096 + n];
    __half hi = __float2half_rn(v);
    float lo = v - __half2float(hi);
    __nv_fp8_e4m3 q(lo * LO_SCALE);
    g_Bh[np * 1024 + k] = hi;
    g_Bq[np * 1024 + k] = *reinterpret_cast<uint8_t*>(&q);
    if (k == 0) { g_kwP[np] = Kw[n]; g_biasP[np] = bias[n]; }
}

__global__ void zero_kernel() {
    int i = blockIdx.x * blockDim.x + threadIdx.x;
    if (i < BATCH * UNITS) {
        g_c[i] = 0.0f;
        if (i < BATCH * 512)  ((uint32_t*)g_Ah[0])[i] = 0;
        if (i < BATCH * 256)  ((uint32_t*)g_Aq[0])[i] = 0;
    }
}

// ---------------- fused LSTM step (fp8 lo GEMM + fp16 hi GEMM + gates) ----------------
__global__ void __launch_bounds__(NTHREADS, 2) lstm_mma(const float* __restrict__ xsrc,
                                                        int xstride, int pin) {
    extern __shared__ char smem[];
    const uint32_t sb = smem_u32(smem);
    const int tid  = threadIdx.x;
    const int wid  = tid >> 5;
    const int lane = tid & 31;
    const int wm   = wid >> 1;       // 0..3 (32-row group)
    const int wn   = wid & 1;        // 0..1 (64-col group)
    const int krot = wid & 3;        // kk-phase rotation per warp
    const int m0   = blockIdx.x * BM;
    const int n0p  = blockIdx.y * BN;   // permuted-col base

    const __half*  __restrict__ Ah = g_Ah[pin];
    const uint8_t* __restrict__ Aq = g_Aq[pin];
    __half*  __restrict__ AhOut = g_Ah[pin ^ 1];
    uint8_t* __restrict__ AqOut = g_Aq[pin ^ 1];

    float acc[2][8][4];
    #pragma unroll
    for (int a = 0; a < 2; a++)
        #pragma unroll
        for (int b = 0; b < 8; b++)
            #pragma unroll
            for (int c = 0; c < 4; c++) acc[a][b][c] = 0.0f;

    const int cprow = tid >> 3;     // 0..31
    const int cpch  = tid & 7;

    auto issue = [&](int s) {
        const uint32_t ab = sb + (s % NBUF) * STG_BYTES;
        const uint32_t bb = ab + A_STG;
        if (s < NF8) {   // fp8 stage: 128 bytes of k per row
            const int kB = s * 128;
            #pragma unroll
            for (int p = 0; p < 4; p++) {
                int row = cprow + p * 32;
                uint32_t sa = ab + row * 128 + ((cpch ^ (row & 7)) << 4);
                cp16(sa, &Aq[(m0 + row) * 1024 + kB + cpch * 16]);
            }
            #pragma unroll
            for (int p = 0; p < 4; p++) {
                int row = cprow + p * 32;
                uint32_t sa = bb + row * 128 + ((cpch ^ (row & 7)) << 4);
                cp16(sa, &g_Bq[(uint64_t)(n0p + row) * 1024 + kB + cpch * 16]);
            }
        } else {         // fp16 stage: 64 halfs of k per row
            const int kB = (s - NF8) * 64;
            #pragma unroll
            for (int p = 0; p < 4; p++) {
                int row = cprow + p * 32;
                uint32_t sa = ab + row * 128 + ((cpch ^ (row & 7)) << 4);
                cp16(sa, &Ah[(m0 + row) * 1024 + kB + cpch * 8]);
            }
            #pragma unroll
            for (int p = 0; p < 4; p++) {
                int row = cprow + p * 32;
                uint32_t sa = bb + row * 128 + ((cpch ^ (row & 7)) << 4);
                cp16(sa, &g_Bh[(uint64_t)(n0p + row) * 1024 + kB + cpch * 8]);
            }
        }
        cp_commit();
    };

    // fragment lane mapping (identical for both phases — byte-quad structure matches)
    const int a_r  = lane & 15;
    const int a_cb = lane >> 4;
    const int b_rr = (lane & 7) + ((lane >> 4) << 3);
    const int b_cb = (lane >> 3) & 1;

    issue(0);
    issue(1);

    #pragma unroll 1
    for (int s = 0; s < NSTG; s++) {
        if (s == NSTG - 1) cp_wait<0>();
        else               cp_wait<1>();   // stage s landed
        __syncthreads();                   // data visible + slot (s-1)%NBUF free
        if (s + 2 < NSTG) issue(s + 2);    // prefetch 2 ahead into freed slot

        const uint32_t ab = sb + (s % NBUF) * STG_BYTES;
        const uint32_t bb = ab + A_STG;

        #pragma unroll
        for (int kk = 0; kk < 4; kk++) {
            const int kq = (kk + krot) & 3;   // per-warp phase rotation
            uint32_t af[2][4], bf[4][4];
            {
                int ch = kq * 2 + a_cb;
                #pragma unroll
                for (int mi = 0; mi < 2; mi++) {
                    int row = wm * 32 + mi * 16 + a_r;
                    ldsm4(af[mi], ab + row * 128 + ((ch ^ (row & 7)) << 4));
                }
            }
            {
                int ch = kq * 2 + b_cb;
                #pragma unroll
                for (int jp = 0; jp < 4; jp++) {
                    int row = wn * 64 + jp * 16 + b_rr;
                    ldsm4(bf[jp], bb + row * 128 + ((ch ^ (row & 7)) << 4));
                }
            }
            if (s < NF8) {
                #pragma unroll
                for (int mi = 0; mi < 2; mi++)
                    #pragma unroll
                    for (int j = 0; j < 8; j++)
                        qmma16832(acc[mi][j], af[mi], &bf[j >> 1][(j & 1) * 2]);
            } else {
                #pragma unroll
                for (int mi = 0; mi < 2; mi++)
                    #pragma unroll
                    for (int j = 0; j < 8; j++)
                        mma16816(acc[mi][j], af[mi], &bf[j >> 1][(j & 1) * 2]);
            }
        }
        if (s == NF8 - 1) {   // lo GEMM done: fold in the 2^-20 scale
            #pragma unroll
            for (int a = 0; a < 2; a++)
                #pragma unroll
                for (int b = 0; b < 8; b++)
                    #pragma unroll
                    for (int c = 0; c < 4; c++) acc[a][b][c] *= LO_UNSCALE;
        }
    }

    // ---------------- epilogue ----------------
    const int q  = lane & 3;
    const int tr = lane >> 2;
    float kwv[8][2], bsv[8][2];
    #pragma unroll
    for (int j = 0; j < 8; j++) {
        int C = n0p + wn * 64 + 8 * j + 2 * q;
        float2 kw2 = *reinterpret_cast<const float2*>(&g_kwP[C]);
        float2 bs2 = *reinterpret_cast<const float2*>(&g_biasP[C]);
        kwv[j][0] = kw2.x; kwv[j][1] = kw2.y;
        bsv[j][0] = bs2.x; bsv[j][1] = bs2.y;
    }
    // global 64-col-group index = blockIdx.y*2 + wn; 16 units per group
    const int u0 = (blockIdx.y * 2 + wn) * 16 + 4 * q;   // 4 consecutive units

    #pragma unroll
    for (int mi = 0; mi < 2; mi++) {
        #pragma unroll
        for (int h = 0; h < 2; h++) {
            int row = m0 + wm * 32 + mi * 16 + tr + 8 * h;
            float xb = xsrc ? xsrc[row * xstride] : g_pred[row];
            float4 cold = *reinterpret_cast<const float4*>(&g_c[row * 1024 + u0]);
            float co[4] = {cold.x, cold.y, cold.z, cold.w};
            float cn[4], hf[4];
            __half hh4[4];
            #pragma unroll
            for (int jl = 0; jl < 4; jl++) {
                float zi = acc[mi][jl    ][2 * h    ] + xb * kwv[jl    ][0] + bsv[jl    ][0];
                float zf = acc[mi][jl    ][2 * h + 1] + xb * kwv[jl    ][1] + bsv[jl    ][1];
                float zg = acc[mi][jl + 4][2 * h    ] + xb * kwv[jl + 4][0] + bsv[jl + 4][0];
                float zo = acc[mi][jl + 4][2 * h + 1] + xb * kwv[jl + 4][1] + bsv[jl + 4][1];
                float ig = sigm(zi);
                float fg = sigm(zf);
                float gg = tanh_fast(zg);
                float og = sigm(zo);
                float cc = fg * co[jl] + ig * gg;
                cn[jl] = cc;
                float hh = og * tanh_fast(cc);
                hf[jl] = hh;
                hh4[jl] = __float2half_rn(hh);
            }
            float4 cv = {cn[0], cn[1], cn[2], cn[3]};
            *reinterpret_cast<float4*>(&g_c[row * 1024 + u0]) = cv;
            uint2 hv;
            memcpy(&hv, hh4, 8);
            *reinterpret_cast<uint2*>(&AhOut[row * 1024 + u0]) = hv;
            uint32_t qw;
            asm("{ .reg .b16 l, h;\n\t"
                "cvt.rn.satfinite.e4m3x2.f32 l, %2, %1;\n\t"
                "cvt.rn.satfinite.e4m3x2.f32 h, %4, %3;\n\t"
                "mov.b32 %0, {l, h}; }"
                : "=r"(qw) : "f"(hf[0]), "f"(hf[1]), "f"(hf[2]), "f"(hf[3]));
            *reinterpret_cast<uint32_t*>(&AqOut[row * 1024 + u0]) = qw;
        }
    }
}

// ---------------- prediction head ----------------
__global__ void __launch_bounds__(256) pred_kernel(
    const float* __restrict__ w1, const float* __restrict__ b1,
    const float* __restrict__ w2, const float* __restrict__ b2,
    float* __restrict__ out, int tcol, int pin, int final_dense)
{
    int warp = (blockIdx.x * blockDim.x + threadIdx.x) >> 5;
    int lane = threadIdx.x & 31;
    if (warp >= BATCH) return;
    const __half* __restrict__ ha = &g_Ah[pin][warp * 1024];
    float s = 0.0f;
    #pragma unroll 4
    for (int k = lane; k < UNITS; k += 32)
        s = fmaf(__half2float(ha[k]), w1[k], s);
    #pragma unroll
    for (int off = 16; off; off >>= 1) s += __shfl_down_sync(0xffffffffu, s, off);
    if (lane == 0) {
        float x = fmaxf(s + b1[0], 0.0f);
        float p = final_dense ? fmaf(x, w2[0], b2[0]) : x;
        out[warp * OUT_STEPS + tcol] = p;
        g_pred[warp] = p;
    }
}

extern "C" void kernel_launch(void* const* d_in, const int* in_sizes, int n_in,
                              void* d_out, int out_size)
{
    const float* inputs = (const float*)d_in[0];
    const float* Kw     = (const float*)d_in[1];
    const float* R      = (const float*)d_in[2];
    const float* bias   = (const float*)d_in[3];
    const float* w1     = (const float*)d_in[4];
    const float* b1     = (const float*)d_in[5];
    const float* w2     = (const float*)d_in[6];
    const float* b2     = (const float*)d_in[7];
    float* out = (float*)d_out;

    cudaFuncSetAttribute(lstm_mma, cudaFuncAttributeMaxDynamicSharedMemorySize, SMEM_TOTAL);

    zero_kernel<<<(BATCH * UNITS + 255) / 256, 256>>>();
    prep_kernel<<<(4096 * 1024 + 255) / 256, 256>>>(R, Kw, bias);

    dim3 grid(BATCH / BM, 4096 / BN);   // (32, 32)
    int pp = 0;

    for (int t = 0; t < SEQ_LEN; t++) {
        lstm_mma<<<grid, NTHREADS, SMEM_TOTAL>>>(inputs + t, SEQ_LEN, pp);
        pp ^= 1;
    }
    pred_kernel<<<BATCH / 8, 256>>>(w1, b1, w2, b2, out, 0, pp, 0);

    for (int j = 1; j < OUT_STEPS; j++) {
        lstm_mma<<<grid, NTHREADS, SMEM_TOTAL>>>(nullptr, 1, pp);
        pp ^= 1;
        pred_kernel<<<BATCH / 8, 256>>>(w1, b1, w2, b2, out, j, pp, 1);
    }
}

// round 10
// speedup vs baseline: 1.4182x; 1.4182x over previous
#include <cuda_runtime.h>
#include <cuda_fp16.h>
#include <math.h>
#include <cstdint>

#define BATCH 4096
#define UNITS 1024
#define OUT_STEPS 200
#define SEQ_LEN 5

#define BK 64
#define NSTG 16          // merged stages: each does k64 against B_hi AND B_lo
#define BM 128
#define BN 128           // permuted z columns (= 32 units x 4 gates)
#define NTHREADS 256

#define A_STG 16384                     // 128 rows x 128B (k64 fp16)
#define STG_BYTES (3 * 16384)           // A + B_hi + B_lo = 48KB
#define NBUF 2
#define SMEM_TOTAL (NBUF * STG_BYTES)   // 96KB -> 2 CTAs/SM

// ---------------- device globals ----------------
__device__ __half g_A[2][BATCH * 1024];   // ping-pong hidden state, fp16
__device__ __half g_B[4096 * 2048];       // permuted split R: row C, [R_hi(1024) | R_lo(1024)]
__device__ float g_c[BATCH * UNITS];
__device__ float g_pred[BATCH];
__device__ float g_kwP[4096];
__device__ float g_biasP[4096];

// ---------------- helpers ----------------
__device__ __forceinline__ uint32_t smem_u32(const void* p) {
    uint32_t a;
    asm("{ .reg .u64 t; cvta.to.shared.u64 t, %1; cvt.u32.u64 %0, t; }" : "=r"(a) : "l"(p));
    return a;
}
__device__ __forceinline__ void cp16(uint32_t saddr, const void* gaddr) {
    asm volatile("cp.async.cg.shared.global [%0], [%1], 16;" :: "r"(saddr), "l"(gaddr));
}
__device__ __forceinline__ void cp_commit() {
    asm volatile("cp.async.commit_group;" ::: "memory");
}
template<int N> __device__ __forceinline__ void cp_wait() {
    asm volatile("cp.async.wait_group %0;" :: "n"(N) : "memory");
}
__device__ __forceinline__ void ldsm4(uint32_t* r, uint32_t addr) {
    asm volatile("ldmatrix.sync.aligned.m8n8.x4.shared.b16 {%0,%1,%2,%3}, [%4];"
                 : "=r"(r[0]), "=r"(r[1]), "=r"(r[2]), "=r"(r[3]) : "r"(addr));
}
__device__ __forceinline__ void mma16816(float* c, const uint32_t* a, const uint32_t* b) {
    asm volatile(
        "mma.sync.aligned.m16n8k16.row.col.f32.f16.f16.f32 "
        "{%0,%1,%2,%3}, {%4,%5,%6,%7}, {%8,%9}, {%0,%1,%2,%3};"
        : "+f"(c[0]), "+f"(c[1]), "+f"(c[2]), "+f"(c[3])
        : "r"(a[0]), "r"(a[1]), "r"(a[2]), "r"(a[3]), "r"(b[0]), "r"(b[1]));
}
__device__ __forceinline__ float sigm(float x) { return 1.0f / (1.0f + __expf(-x)); }
__device__ __forceinline__ float tanh_fast(float x) {
    float t = __expf(-2.0f * fabsf(x));
    float r = (1.0f - t) / (1.0f + t);
    return copysignf(r, x);
}

// ---------------- prep: build permuted split-fp16 B ----------------
// Permuted column C <- (unit u, gate g):
//   C = (u>>4)*64 + (g>>1)*32 + (u&3)*8 + ((u>>2)&3)*2 + (g&1)
// Inverse: u = (C>>6)*16 + ((C>>1)&3)*4 + ((C>>3)&3) ; g = ((C>>5)&1)*2 + (C&1)
__global__ void prep_kernel(const float* __restrict__ R, const float* __restrict__ Kw,
                            const float* __restrict__ bias) {
    int idx = blockIdx.x * blockDim.x + threadIdx.x;   // np*1024 + k
    if (idx >= 4096 * 1024) return;
    int np = idx >> 10;
    int k  = idx & 1023;
    int u = ((np >> 6) << 4) | (((np >> 1) & 3) << 2) | ((np >> 3) & 3);
    int g = (((np >> 5) & 1) << 1) | (np & 1);
    int n = g * 1024 + u;
    float v = R[k * 4096 + n];
    __half hi = __float2half_rn(v);
    __half lo = __float2half_rn(v - __half2float(hi));
    g_B[np * 2048 + k]        = hi;
    g_B[np * 2048 + 1024 + k] = lo;
    if (k == 0) { g_kwP[np] = Kw[n]; g_biasP[np] = bias[n]; }
}

__global__ void zero_kernel() {
    int i = blockIdx.x * blockDim.x + threadIdx.x;
    if (i < BATCH * UNITS) {
        g_c[i] = 0.0f;
        if (i < BATCH * 512) ((uint32_t*)g_A[0])[i] = 0;   // 2M halfs
    }
}

// ---------------- fused LSTM step (fp16 mma.sync dual-B GEMM + gates) ----------------
__global__ void __launch_bounds__(NTHREADS, 2) lstm_mma(const float* __restrict__ xsrc,
                                                        int xstride, int pin) {
    extern __shared__ char smem[];
    const uint32_t sb = smem_u32(smem);
    const int tid  = threadIdx.x;
    const int wid  = tid >> 5;
    const int lane = tid & 31;
    const int wm   = wid >> 1;       // 0..3 (32-row group)
    const int wn   = wid & 1;        // 0..1 (64-col group)
    const int krot = wid & 3;        // kk-phase rotation per warp
    const int m0   = blockIdx.x * BM;
    const int n0p  = blockIdx.y * BN;   // permuted-col base

    const __half* __restrict__ Ain = g_A[pin];
    __half* __restrict__ Aout = g_A[pin ^ 1];

    float acc[2][8][4];
    #pragma unroll
    for (int a = 0; a < 2; a++)
        #pragma unroll
        for (int b = 0; b < 8; b++)
            #pragma unroll
            for (int c = 0; c < 4; c++) acc[a][b][c] = 0.0f;

    const int cprow = tid >> 3;     // 0..31
    const int cpch  = tid & 7;

    auto issue = [&](int s) {
        const int buf = s & (NBUF - 1);
        const int kk0 = s * BK;
        const uint32_t ab = sb + buf * STG_BYTES;
        const uint32_t bh = ab + A_STG;
        const uint32_t bl = ab + 2 * A_STG;
        #pragma unroll
        for (int p = 0; p < 4; p++) {                 // A: 128 rows of k64
            int row = cprow + p * 32;
            uint32_t so = row * 128 + ((cpch ^ (row & 7)) << 4);
            cp16(ab + so, &Ain[(m0 + row) * 1024 + kk0 + cpch * 8]);
        }
        #pragma unroll
        for (int p = 0; p < 4; p++) {                 // B_hi: 128 rows
            int row = cprow + p * 32;
            uint32_t so = row * 128 + ((cpch ^ (row & 7)) << 4);
            cp16(bh + so, &g_B[(uint64_t)(n0p + row) * 2048 + kk0 + cpch * 8]);
        }
        #pragma unroll
        for (int p = 0; p < 4; p++) {                 // B_lo: 128 rows
            int row = cprow + p * 32;
            uint32_t so = row * 128 + ((cpch ^ (row & 7)) << 4);
            cp16(bl + so, &g_B[(uint64_t)(n0p + row) * 2048 + 1024 + kk0 + cpch * 8]);
        }
        cp_commit();
    };

    // fragment lane mapping
    const int a_r  = lane & 15;
    const int a_cb = lane >> 4;
    const int b_rr = (lane & 7) + ((lane >> 4) << 3);
    const int b_cb = (lane >> 3) & 1;

    issue(0);

    #pragma unroll 1
    for (int s = 0; s < NSTG; s++) {
        cp_wait<0>();                      // stage s landed (only one group in flight)
        __syncthreads();                   // all warps done with buf s^1 & see stage s
        if (s + 1 < NSTG) issue(s + 1);    // prefetch next into the freed slot

        const uint32_t ab = sb + (s & (NBUF - 1)) * STG_BYTES;
        const uint32_t bh = ab + A_STG;
        const uint32_t bl = ab + 2 * A_STG;

        #pragma unroll
        for (int kk = 0; kk < 4; kk++) {
            const int kq = (kk + krot) & 3;   // per-warp phase rotation
            uint32_t af[2][4], bf[4][4];
            {
                int ch = kq * 2 + a_cb;
                #pragma unroll
                for (int mi = 0; mi < 2; mi++) {
                    int row = wm * 32 + mi * 16 + a_r;
                    ldsm4(af[mi], ab + row * 128 + ((ch ^ (row & 7)) << 4));
                }
            }
            // B_hi burst
            {
                int ch = kq * 2 + b_cb;
                #pragma unroll
                for (int jp = 0; jp < 4; jp++) {
                    int row = wn * 64 + jp * 16 + b_rr;
                    ldsm4(bf[jp], bh + row * 128 + ((ch ^ (row & 7)) << 4));
                }
            }
            #pragma unroll
            for (int mi = 0; mi < 2; mi++)
                #pragma unroll
                for (int j = 0; j < 8; j++)
                    mma16816(acc[mi][j], af[mi], &bf[j >> 1][(j & 1) * 2]);
            // B_lo burst (reuse A frags and bf registers)
            {
                int ch = kq * 2 + b_cb;
                #pragma unroll
                for (int jp = 0; jp < 4; jp++) {
                    int row = wn * 64 + jp * 16 + b_rr;
                    ldsm4(bf[jp], bl + row * 128 + ((ch ^ (row & 7)) << 4));
                }
            }
            #pragma unroll
            for (int mi = 0; mi < 2; mi++)
                #pragma unroll
                for (int j = 0; j < 8; j++)
                    mma16816(acc[mi][j], af[mi], &bf[j >> 1][(j & 1) * 2]);
        }
    }

    // ---------------- epilogue ----------------
    const int q  = lane & 3;
    const int tr = lane >> 2;
    float kwv[8][2], bsv[8][2];
    #pragma unroll
    for (int j = 0; j < 8; j++) {
        int C = n0p + wn * 64 + 8 * j + 2 * q;
        float2 kw2 = *reinterpret_cast<const float2*>(&g_kwP[C]);
        float2 bs2 = *reinterpret_cast<const float2*>(&g_biasP[C]);
        kwv[j][0] = kw2.x; kwv[j][1] = kw2.y;
        bsv[j][0] = bs2.x; bsv[j][1] = bs2.y;
    }
    // global 64-col-group index = blockIdx.y*2 + wn; 16 units per group
    const int u0 = (blockIdx.y * 2 + wn) * 16 + 4 * q;   // 4 consecutive units

    #pragma unroll
    for (int mi = 0; mi < 2; mi++) {
        #pragma unroll
        for (int h = 0; h < 2; h++) {
            int row = m0 + wm * 32 + mi * 16 + tr + 8 * h;
            float xb = xsrc ? xsrc[row * xstride] : g_pred[row];
            float4 cold = *reinterpret_cast<const float4*>(&g_c[row * 1024 + u0]);
            float co[4] = {cold.x, cold.y, cold.z, cold.w};
            float cn[4];
            __half hh4[4];
            #pragma unroll
            for (int jl = 0; jl < 4; jl++) {
                float zi = acc[mi][jl    ][2 * h    ] + xb * kwv[jl    ][0] + bsv[jl    ][0];
                float zf = acc[mi][jl    ][2 * h + 1] + xb * kwv[jl    ][1] + bsv[jl    ][1];
                float zg = acc[mi][jl + 4][2 * h    ] + xb * kwv[jl + 4][0] + bsv[jl + 4][0];
                float zo = acc[mi][jl + 4][2 * h + 1] + xb * kwv[jl + 4][1] + bsv[jl + 4][1];
                float ig = sigm(zi);
                float fg = sigm(zf);
                float gg = tanh_fast(zg);
                float og = sigm(zo);
                float cc = fg * co[jl] + ig * gg;
                cn[jl] = cc;
                float hh = og * tanh_fast(cc);
                hh4[jl] = __float2half_rn(hh);
            }
            float4 cv = {cn[0], cn[1], cn[2], cn[3]};
            *reinterpret_cast<float4*>(&g_c[row * 1024 + u0]) = cv;
            uint2 hv;
            memcpy(&hv, hh4, 8);
            *reinterpret_cast<uint2*>(&Aout[row * 1024 + u0]) = hv;
        }
    }
}

// ---------------- prediction head ----------------
__global__ void __launch_bounds__(256) pred_kernel(
    const float* __restrict__ w1, const float* __restrict__ b1,
    const float* __restrict__ w2, const float* __restrict__ b2,
    float* __restrict__ out, int tcol, int pin, int final_dense)
{
    int warp = (blockIdx.x * blockDim.x + threadIdx.x) >> 5;
    int lane = threadIdx.x & 31;
    if (warp >= BATCH) return;
    const __half* __restrict__ ha = &g_A[pin][warp * 1024];
    float s = 0.0f;
    #pragma unroll 4
    for (int k = lane; k < UNITS; k += 32)
        s = fmaf(__half2float(ha[k]), w1[k], s);
    #pragma unroll
    for (int off = 16; off; off >>= 1) s += __shfl_down_sync(0xffffffffu, s, off);
    if (lane == 0) {
        float x = fmaxf(s + b1[0], 0.0f);
        float p = final_dense ? fmaf(x, w2[0], b2[0]) : x;
        out[warp * OUT_STEPS + tcol] = p;
        g_pred[warp] = p;
    }
}

extern "C" void kernel_launch(void* const* d_in, const int* in_sizes, int n_in,
                              void* d_out, int out_size)
{
    const float* inputs = (const float*)d_in[0];
    const float* Kw     = (const float*)d_in[1];
    const float* R      = (const float*)d_in[2];
    const float* bias   = (const float*)d_in[3];
    const float* w1     = (const float*)d_in[4];
    const float* b1     = (const float*)d_in[5];
    const float* w2     = (const float*)d_in[6];
    const float* b2     = (const float*)d_in[7];
    float* out = (float*)d_out;

    cudaFuncSetAttribute(lstm_mma, cudaFuncAttributeMaxDynamicSharedMemorySize, SMEM_TOTAL);

    zero_kernel<<<(BATCH * UNITS + 255) / 256, 256>>>();
    prep_kernel<<<(4096 * 1024 + 255) / 256, 256>>>(R, Kw, bias);

    dim3 grid(BATCH / BM, 4096 / BN);   // (32, 32)
    int pp = 0;

    for (int t = 0; t < SEQ_LEN; t++) {
        lstm_mma<<<grid, NTHREADS, SMEM_TOTAL>>>(inputs + t, SEQ_LEN, pp);
        pp ^= 1;
    }
    pred_kernel<<<BATCH / 8, 256>>>(w1, b1, w2, b2, out, 0, pp, 0);

    for (int j = 1; j < OUT_STEPS; j++) {
        lstm_mma<<<grid, NTHREADS, SMEM_TOTAL>>>(nullptr, 1, pp);
        pp ^= 1;
        pred_kernel<<<BATCH / 8, 256>>>(w1, b1, w2, b2, out, j, pp, 1);
    }
}